// round 9
// baseline (speedup 1.0000x reference)
#include <cuda_runtime.h>
#include <math.h>

#define TBL 512
#define THREADS 256
#define CHUNK 8          // patches per thread, loads issued up-front (MLP=8)
#define PER_BLOCK (THREADS * CHUNK)   // 2048 patches per block

// ---------------- accurate scalar chain F(s) (used for in-kernel tabulation) ----------------
__device__ __forceinline__ float eval_chain(float s,
                                            const float* __restrict__ Wl,
                                            const float* __restrict__ bl,
                                            const float* __restrict__ scale,
                                            const float* __restrict__ shift,
                                            const float* __restrict__ Wf,
                                            const float* __restrict__ bf)
{
    float x0 = s, x1 = 0.0f;
#pragma unroll
    for (int l = 0; l < 5; l++) {
        float y0 = tanhf(fmaf(x0, __ldg(Wl + 4 * l + 0), fmaf(x1, __ldg(Wl + 4 * l + 1), __ldg(bl + 2 * l + 0))));
        float y1 = tanhf(fmaf(x0, __ldg(Wl + 4 * l + 2), fmaf(x1, __ldg(Wl + 4 * l + 3), __ldg(bl + 2 * l + 1))));
        x0 = fmaf(y0, __ldg(scale + 2 * l + 0), __ldg(shift + 2 * l + 0));
        x1 = fmaf(y1, __ldg(scale + 2 * l + 1), __ldg(shift + 2 * l + 1));
    }
    return fmaf(x0, __ldg(Wf + 0), fmaf(x1, __ldg(Wf + 1), __ldg(bf)));
}

// ---------------- single fused kernel: tabulate (per-CTA) + stream ----------------
__global__ __launch_bounds__(THREADS, 5)
void fraud_kernel(const float4* __restrict__ data,
                  const float* __restrict__ Wc, const float* __restrict__ bc,
                  const float* __restrict__ Wl, const float* __restrict__ bl,
                  const float* __restrict__ scale, const float* __restrict__ shift,
                  const float* __restrict__ Wf, const float* __restrict__ bf,
                  float* __restrict__ out, int B)
{
    __shared__ float  vals[TBL + 1];   // 2052 B scratch
    __shared__ float2 tab[TBL];        // 4 KB lerp table

    const int tid = threadIdx.x;
    const int base = blockIdx.x * PER_BLOCK + tid;

    // ---- 1) issue the 8 streaming loads FIRST: DRAM traffic starts immediately ----
    float4 d[CHUNK];
#pragma unroll
    for (int k = 0; k < CHUNK; k++) {
        const int i = base + k * THREADS;
        if (i < B) d[k] = __ldcs(data + i);   // 8 independent LDG.128 -> MLP=8
    }

    // ---- 2) tabulate F(s) in the shadow of those loads (accurate tanhf) ----
    {
        const float inv = 1.0f / (float)TBL;
        vals[tid]           = eval_chain((float)tid * inv,          Wl, bl, scale, shift, Wf, bf);
        vals[tid + THREADS] = eval_chain((float)(tid + THREADS) * inv, Wl, bl, scale, shift, Wf, bf);
        if (tid == 0)
            vals[TBL] = eval_chain(1.0f, Wl, bl, scale, shift, Wf, bf);
    }

    // fold -log2(e) into conv weights:  s = 1/(1 + 2^(z'))  with z' = -log2(e)*(conv+bias)
    const float NL2E = -1.4426950408889634f;
    const float wc0 = __ldg(Wc + 0) * NL2E, wc1 = __ldg(Wc + 1) * NL2E;
    const float wc2 = __ldg(Wc + 2) * NL2E, wc3 = __ldg(Wc + 3) * NL2E;
    const float bcv = __ldg(bc) * NL2E;

    __syncthreads();

    // build {value, delta} pairs
#pragma unroll
    for (int j = tid; j < TBL; j += THREADS)
        tab[j] = make_float2(vals[j], vals[j + 1] - vals[j]);

    __syncthreads();

    // ---- 3) consume: conv + sigmoid + table lerp ----
#pragma unroll
    for (int k = 0; k < CHUNK; k++) {
        const int i = base + k * THREADS;
        if (i >= B) continue;

        const float zp = fmaf(d[k].x, wc0, fmaf(d[k].y, wc1,
                         fmaf(d[k].z, wc2, fmaf(d[k].w, wc3, bcv))));
        float e;
        asm("ex2.approx.f32 %0, %1;" : "=f"(e) : "f"(zp));
        float s;
        asm("rcp.approx.f32 %0, %1;" : "=f"(s) : "f"(e + 1.0f));

        float t = s * (float)TBL;            // t in [0, TBL]
        int idx = (int)t;
        idx = min(idx, TBL - 1);
        const float f = t - (float)idx;
        const float2 v = tab[idx];
        __stcs(out + i, fmaf(v.y, f, v.x));
    }
}

extern "C" void kernel_launch(void* const* d_in, const int* in_sizes, int n_in,
                              void* d_out, int out_size)
{
    const float4* data  = (const float4*)d_in[0];
    const float*  Wc    = (const float*)d_in[1];
    const float*  bc    = (const float*)d_in[2];
    const float*  Wl    = (const float*)d_in[3];
    const float*  bl    = (const float*)d_in[4];
    const float*  scale = (const float*)d_in[5];
    const float*  shift = (const float*)d_in[6];
    const float*  Wf    = (const float*)d_in[7];
    const float*  bf    = (const float*)d_in[8];
    float* out = (float*)d_out;

    const int B = in_sizes[0] / 4;          // 4 floats per patch

    int blocks = (B + PER_BLOCK - 1) / PER_BLOCK;
    if (blocks < 1) blocks = 1;
    fraud_kernel<<<blocks, THREADS>>>(data, Wc, bc, Wl, bl, scale, shift, Wf, bf, out, B);
}

// round 10
// speedup vs baseline: 1.0664x; 1.0664x over previous
#include <cuda_runtime.h>
#include <math.h>

#define TBL 512
#define THREADS 256
#define CHUNK 8          // patches per thread, loads issued up-front (MLP=8)
#define PER_BLOCK (THREADS * CHUNK)   // 2048 patches per block

// tanh via ex2 + rcp:  tanh(y) = 1 - 2/(exp(2y)+1).  abs err ~1e-7, saturates correctly.
__device__ __forceinline__ float fast_tanh(float y) {
    float e;
    asm("ex2.approx.f32 %0, %1;" : "=f"(e) : "f"(y * 2.8853900817779268f)); // 2*log2(e)
    float r;
    asm("rcp.approx.f32 %0, %1;" : "=f"(r) : "f"(e + 1.0f));
    return fmaf(-2.0f, r, 1.0f);
}

// ---------------- scalar chain F(s) via fast_tanh (proven rel_err ~6e-8 in R2) ----------------
__device__ __forceinline__ float eval_chain(float s,
                                            const float* __restrict__ Wl,
                                            const float* __restrict__ bl,
                                            const float* __restrict__ scale,
                                            const float* __restrict__ shift,
                                            const float* __restrict__ Wf,
                                            const float* __restrict__ bf)
{
    float x0 = s, x1 = 0.0f;
#pragma unroll
    for (int l = 0; l < 5; l++) {
        float y0 = fast_tanh(fmaf(x0, __ldg(Wl + 4 * l + 0), fmaf(x1, __ldg(Wl + 4 * l + 1), __ldg(bl + 2 * l + 0))));
        float y1 = fast_tanh(fmaf(x0, __ldg(Wl + 4 * l + 2), fmaf(x1, __ldg(Wl + 4 * l + 3), __ldg(bl + 2 * l + 1))));
        x0 = fmaf(y0, __ldg(scale + 2 * l + 0), __ldg(shift + 2 * l + 0));
        x1 = fmaf(y1, __ldg(scale + 2 * l + 1), __ldg(shift + 2 * l + 1));
    }
    return fmaf(x0, __ldg(Wf + 0), fmaf(x1, __ldg(Wf + 1), __ldg(bf)));
}

// ---------------- single fused kernel: cheap per-CTA tabulation + stream ----------------
__global__ __launch_bounds__(THREADS, 5)
void fraud_kernel(const float4* __restrict__ data,
                  const float* __restrict__ Wc, const float* __restrict__ bc,
                  const float* __restrict__ Wl, const float* __restrict__ bl,
                  const float* __restrict__ scale, const float* __restrict__ shift,
                  const float* __restrict__ Wf, const float* __restrict__ bf,
                  float* __restrict__ out, int B)
{
    __shared__ float  vals[TBL + 1];   // scratch
    __shared__ float2 tab[TBL];        // 4 KB lerp table

    const int tid = threadIdx.x;
    const int base = blockIdx.x * PER_BLOCK + tid;

    // ---- 1) issue the 8 streaming loads FIRST: DRAM traffic starts immediately ----
    float4 d[CHUNK];
#pragma unroll
    for (int k = 0; k < CHUNK; k++) {
        const int i = base + k * THREADS;
        if (i < B) d[k] = __ldcs(data + i);   // 8 independent LDG.128 -> MLP=8
    }

    // ---- 2) tabulate F(s) with the CHEAP chain (2 evals/thread, ~40 MUFU) ----
    {
        const float inv = 1.0f / (float)TBL;
        vals[tid]           = eval_chain((float)tid * inv,             Wl, bl, scale, shift, Wf, bf);
        vals[tid + THREADS] = eval_chain((float)(tid + THREADS) * inv, Wl, bl, scale, shift, Wf, bf);
        if (tid == 0)
            vals[TBL] = eval_chain(1.0f, Wl, bl, scale, shift, Wf, bf);
    }

    // fold -log2(e) into conv weights:  s = 1/(1 + 2^(z'))  with z' = -log2(e)*(conv+bias)
    const float NL2E = -1.4426950408889634f;
    const float wc0 = __ldg(Wc + 0) * NL2E, wc1 = __ldg(Wc + 1) * NL2E;
    const float wc2 = __ldg(Wc + 2) * NL2E, wc3 = __ldg(Wc + 3) * NL2E;
    const float bcv = __ldg(bc) * NL2E;

    __syncthreads();

    // build {value, delta} pairs
#pragma unroll
    for (int j = tid; j < TBL; j += THREADS)
        tab[j] = make_float2(vals[j], vals[j + 1] - vals[j]);

    __syncthreads();

    // ---- 3) consume: conv + sigmoid + table lerp ----
#pragma unroll
    for (int k = 0; k < CHUNK; k++) {
        const int i = base + k * THREADS;
        if (i >= B) continue;

        const float zp = fmaf(d[k].x, wc0, fmaf(d[k].y, wc1,
                         fmaf(d[k].z, wc2, fmaf(d[k].w, wc3, bcv))));
        float e;
        asm("ex2.approx.f32 %0, %1;" : "=f"(e) : "f"(zp));
        float s;
        asm("rcp.approx.f32 %0, %1;" : "=f"(s) : "f"(e + 1.0f));

        float t = s * (float)TBL;            // t in [0, TBL]
        int idx = (int)t;
        idx = min(idx, TBL - 1);
        const float f = t - (float)idx;
        const float2 v = tab[idx];
        __stcs(out + i, fmaf(v.y, f, v.x));
    }
}

extern "C" void kernel_launch(void* const* d_in, const int* in_sizes, int n_in,
                              void* d_out, int out_size)
{
    const float4* data  = (const float4*)d_in[0];
    const float*  Wc    = (const float*)d_in[1];
    const float*  bc    = (const float*)d_in[2];
    const float*  Wl    = (const float*)d_in[3];
    const float*  bl    = (const float*)d_in[4];
    const float*  scale = (const float*)d_in[5];
    const float*  shift = (const float*)d_in[6];
    const float*  Wf    = (const float*)d_in[7];
    const float*  bf    = (const float*)d_in[8];
    float* out = (float*)d_out;

    const int B = in_sizes[0] / 4;          // 4 floats per patch

    int blocks = (B + PER_BLOCK - 1) / PER_BLOCK;
    if (blocks < 1) blocks = 1;
    fraud_kernel<<<blocks, THREADS>>>(data, Wc, bc, Wl, bl, scale, shift, Wf, bf, out, B);
}

// round 11
// speedup vs baseline: 1.5237x; 1.4289x over previous
#include <cuda_runtime.h>
#include <math.h>

#define TBL 1024
#define THREADS 256
#define CHUNK 8          // patches per thread, loads issued up-front (MLP=8)
#define PER_BLOCK (THREADS * CHUNK)   // 2048 patches per block

// Table of the scalar chain F(s), s in [0,1]:  entry i = { F(i/TBL), F((i+1)/TBL)-F(i/TBL) }
__device__ float2 d_tab[TBL];

// ---------------- Kernel 1: tabulate F(s) with accurate tanhf ----------------
__device__ __forceinline__ float eval_chain(float s,
                                            const float* __restrict__ Wl,
                                            const float* __restrict__ bl,
                                            const float* __restrict__ scale,
                                            const float* __restrict__ shift,
                                            const float* __restrict__ Wf,
                                            const float* __restrict__ bf)
{
    float x0 = s, x1 = 0.0f;
#pragma unroll
    for (int l = 0; l < 5; l++) {
        float y0 = tanhf(fmaf(x0, __ldg(Wl + 4 * l + 0), fmaf(x1, __ldg(Wl + 4 * l + 1), __ldg(bl + 2 * l + 0))));
        float y1 = tanhf(fmaf(x0, __ldg(Wl + 4 * l + 2), fmaf(x1, __ldg(Wl + 4 * l + 3), __ldg(bl + 2 * l + 1))));
        x0 = fmaf(y0, __ldg(scale + 2 * l + 0), __ldg(shift + 2 * l + 0));
        x1 = fmaf(y1, __ldg(scale + 2 * l + 1), __ldg(shift + 2 * l + 1));
    }
    return fmaf(x0, __ldg(Wf + 0), fmaf(x1, __ldg(Wf + 1), __ldg(bf)));
}

__global__ void tab_kernel(const float* __restrict__ Wl, const float* __restrict__ bl,
                           const float* __restrict__ scale, const float* __restrict__ shift,
                           const float* __restrict__ Wf, const float* __restrict__ bf)
{
    int j = blockIdx.x * blockDim.x + threadIdx.x;
    if (j >= TBL) return;
    const float inv = 1.0f / (float)TBL;
    float v0 = eval_chain((float)j * inv,       Wl, bl, scale, shift, Wf, bf);
    float v1 = eval_chain((float)(j + 1) * inv, Wl, bl, scale, shift, Wf, bf);
    d_tab[j] = make_float2(v0, v1 - v0);
}

// ---------------- Kernel 2: streaming conv + sigmoid + table lerp ----------------
__global__ __launch_bounds__(THREADS)
void fraud_kernel(const float4* __restrict__ data,
                  const float* __restrict__ Wc, const float* __restrict__ bc,
                  float* __restrict__ out, int B)
{
    __shared__ float2 tab[TBL];   // 8 KB

    const int base = blockIdx.x * PER_BLOCK + threadIdx.x;

    // Issue streaming data loads FIRST so DRAM traffic starts immediately;
    // the table preload + sync then overlaps with their latency.
    float4 d[CHUNK];
#pragma unroll
    for (int k = 0; k < CHUNK; k++) {
        const int i = base + k * THREADS;
        if (i < B) d[k] = __ldcs(data + i);   // 8 independent LDG.128 -> MLP=8, evict-first
    }

    // cooperative table load (8KB: 2 float4 per thread, L2-hot after first wave)
    {
        const float4* src = (const float4*)d_tab;
        float4* dst = (float4*)tab;
#pragma unroll
        for (int i = threadIdx.x; i < TBL / 2; i += THREADS) dst[i] = src[i];
    }

    // fold -log2(e) into conv weights:  s = 1/(1 + 2^(z'))  with z' = -log2(e)*(conv+bias)
    const float NL2E = -1.4426950408889634f;
    const float wc0 = __ldg(Wc + 0) * NL2E, wc1 = __ldg(Wc + 1) * NL2E;
    const float wc2 = __ldg(Wc + 2) * NL2E, wc3 = __ldg(Wc + 3) * NL2E;
    const float bcv = __ldg(bc) * NL2E;

    __syncthreads();

#pragma unroll
    for (int k = 0; k < CHUNK; k++) {
        const int i = base + k * THREADS;
        if (i >= B) continue;

        const float zp = fmaf(d[k].x, wc0, fmaf(d[k].y, wc1,
                         fmaf(d[k].z, wc2, fmaf(d[k].w, wc3, bcv))));
        float e;
        asm("ex2.approx.f32 %0, %1;" : "=f"(e) : "f"(zp));
        float s;
        asm("rcp.approx.f32 %0, %1;" : "=f"(s) : "f"(e + 1.0f));

        float t = s * (float)TBL;            // t in [0, TBL]
        int idx = (int)t;
        idx = min(idx, TBL - 1);
        const float f = t - (float)idx;
        const float2 v = tab[idx];
        // DEFAULT write-back store: let the 16MB output live in the 126MB L2
        // instead of streaming it to DRAM (__stcs = evict-first was forcing
        // early writeback and HBM read/write turnaround).
        out[i] = fmaf(v.y, f, v.x);
    }
}

extern "C" void kernel_launch(void* const* d_in, const int* in_sizes, int n_in,
                              void* d_out, int out_size)
{
    const float4* data  = (const float4*)d_in[0];
    const float*  Wc    = (const float*)d_in[1];
    const float*  bc    = (const float*)d_in[2];
    const float*  Wl    = (const float*)d_in[3];
    const float*  bl    = (const float*)d_in[4];
    const float*  scale = (const float*)d_in[5];
    const float*  shift = (const float*)d_in[6];
    const float*  Wf    = (const float*)d_in[7];
    const float*  bf    = (const float*)d_in[8];
    float* out = (float*)d_out;

    const int B = in_sizes[0] / 4;          // 4 floats per patch

    tab_kernel<<<TBL / 128, 128>>>(Wl, bl, scale, shift, Wf, bf);

    int blocks = (B + PER_BLOCK - 1) / PER_BLOCK;
    if (blocks < 1) blocks = 1;
    fraud_kernel<<<blocks, THREADS>>>(data, Wc, bc, out, B);
}